// round 14
// baseline (speedup 1.0000x reference)
#include <cuda_runtime.h>
#include <cuda_fp16.h>
#include <mma.h>
#include <cstdint>

#define NN 16384
#define EE 524288
#define EPAD (EE + 4 * NN)
#define BB 32
#define DD 64
#define MM 5

using namespace nvcuda;

// ---------------- device scratch (static, allocation-free) ----------------
// fp16 operand buffers, TRANSPOSED layout: buf[(n*32 + b)*64 + d]
__device__ __half g_Xh[(size_t)BB * NN * DD];
__device__ __half g_T1[(size_t)BB * NN * DD];
__device__ __half g_T2[(size_t)BB * NN * DD];
__device__ __half g_T3[(size_t)BB * NN * DD];
__device__ __half g_T4[(size_t)BB * NN * DD];

// NOTE: zero-initialized at module load; re-zeroed by pass1 every call (see k_spmm<ZERO>)
__device__ float g_degr[NN];
__device__ float g_degc[NN];
__device__ int   g_cnt1[NN], g_cnt2[NN];
__device__ int   g_ptr1[NN + 1], g_ptr2[NN + 1];
__device__ int   g_cur1[NN], g_cur2[NN];
__device__ uint2 g_e1[EPAD], g_e2[EPAD];    // packed (src, val-bits)

#define CVT_BLOCKS 65536   // BB*NN*DD/2 half2 elems / 256 threads
#define EDGE_BLOCKS 2048   // EE / 256

// fused: blocks [0,EDGE_BLOCKS) = degree/histogram atomics;
//        blocks [EDGE_BLOCKS, EDGE_BLOCKS+CVT_BLOCKS) = X transpose-convert.
// inputs [b][n][d] fp32 -> g_Xh [(n*32+b)*64+d] fp16 (transpose b<->n)
__global__ void k_pre(const int* __restrict__ rows, const int* __restrict__ cols,
                      const float* __restrict__ adj, const float* __restrict__ X) {
    int bx = blockIdx.x;
    if (bx < EDGE_BLOCKS) {
        int e = bx * 256 + threadIdx.x;
        if (e >= EE) return;
        int r = rows[e], c = cols[e];
        float a = adj[e];
        atomicAdd(&g_degr[r], a);
        atomicAdd(&g_degc[c], a);
        atomicAdd(&g_cnt1[c], 1);   // S1 scatters to cols
        atomicAdd(&g_cnt2[r], 1);   // S2 scatters to rows
    } else {
        int i = (bx - EDGE_BLOCKS) * 256 + threadIdx.x;   // half2 index in TARGET
        if (i >= BB * NN * (DD / 2)) return;
        int dh = i & 31;
        int b  = (i >> 5) & 31;
        int n  = i >> 10;
        float2 v = ((const float2*)X)[((size_t)b * NN + n) * 32 + dh];
        ((__half2*)g_Xh)[i] = __floats2half2_rn(v.x, v.y);
    }
}

// ---------------- single-kernel scan (both CSRs via blockIdx.y) ----------------
__global__ void __launch_bounds__(1024) k_scan() {
    int y = blockIdx.y;
    int bx = blockIdx.x;
    const int* cnt = y ? g_cnt2 : g_cnt1;
    int i = bx * 1024 + threadIdx.x;
    int lane = threadIdx.x & 31, w = threadIdx.x >> 5;
    __shared__ int sh[32];

    // (1) intra-block exclusive scan of padded counts
    int c = (cnt[i] + 3) & ~3;
    int x = c;
#pragma unroll
    for (int o = 1; o < 32; o <<= 1) {
        int t = __shfl_up_sync(0xffffffffu, x, o);
        if (lane >= o) x += t;
    }
    if (lane == 31) sh[w] = x;
    __syncthreads();
    if (w == 0) {
        int t = sh[lane];
#pragma unroll
        for (int o = 1; o < 32; o <<= 1) {
            int u = __shfl_up_sync(0xffffffffu, t, o);
            if (lane >= o) t += u;
        }
        sh[lane] = t;
    }
    __syncthreads();
    int pre = x - c + (w ? sh[w - 1] : 0);   // exclusive prefix within block
    __syncthreads();                          // done with sh as scan buffer

    // (2) global block offset: sum padded counts in [0, bx*1024)
    int part = 0;
    for (int j = threadIdx.x; j < bx * 1024; j += 1024)
        part += (cnt[j] + 3) & ~3;
#pragma unroll
    for (int o = 16; o > 0; o >>= 1)
        part += __shfl_down_sync(0xffffffffu, part, o);
    if (lane == 0) sh[w] = part;
    __syncthreads();
    if (w == 0) {
        int t = sh[lane];
#pragma unroll
        for (int o = 16; o > 0; o >>= 1)
            t += __shfl_down_sync(0xffffffffu, t, o);
        if (lane == 0) sh[0] = t;
    }
    __syncthreads();
    int boff = sh[0];

    // (3) finalize
    int* ptr = y ? g_ptr2 : g_ptr1;
    int* cur = y ? g_cur2 : g_cur1;
    uint2* edges = y ? g_e2 : g_e1;
    int p = boff + pre;
    ptr[i] = p; cur[i] = p;
    int cn = cnt[i], cr = (cn + 3) & ~3;
    for (int q = p + cn; q < p + cr; ++q) edges[q] = make_uint2(0u, 0u);
    if (bx == 15 && threadIdx.x == 1023) ptr[NN] = p + cr;
    float* dg = y ? g_degc : g_degr;
    float d = dg[i];
    dg[i] = (d > 0.f) ? 1.f / d : 0.f;
}

// fused: one edge-list read fills both CSRs (packed 8B stores)
__global__ void k_fill(const int* __restrict__ rows, const int* __restrict__ cols,
                       const float* __restrict__ adj) {
    int e = blockIdx.x * blockDim.x + threadIdx.x;
    if (e >= EE) return;
    int r = rows[e], c = cols[e];
    float a = adj[e];
    int p = atomicAdd(&g_cur1[c], 1);
    g_e1[p] = make_uint2((unsigned)r, __float_as_uint(a * g_degr[r]));
    int q = atomicAdd(&g_cur2[r], 1);
    g_e2[q] = make_uint2((unsigned)c, __float_as_uint(a * g_degc[c]));
}

// ---------------- SpMM (proven mainloop, packed metadata): warp = (dst node, 4 batches) ----------------
__device__ __forceinline__ void acc8(float2* acc, uint4 g, float v) {
    __half2* h = (__half2*)&g;
#pragma unroll
    for (int k = 0; k < 4; ++k) {
        float2 f = __half22float2(h[k]);
        acc[k].x = fmaf(v, f.x, acc[k].x);
        acc[k].y = fmaf(v, f.y, acc[k].y);
    }
}

// shared mainloop: accumulates 4-batch slice for dst n over [p0,p1)
__device__ __forceinline__ void spmm_body(
    const uint2* __restrict__ edges, const uint4* __restrict__ Xb,
    int p0, int p1, int lane, int sub, float2* acc)
{
    for (int base = p0; base < p1; base += 32) {
        int idx = base + lane;
        int s = 0; float v = 0.f;
        if (idx < p1) {
            uint2 e = edges[idx];          // one LDG.64
            s = (int)e.x; v = __uint_as_float(e.y);
        }
        int cnt = min(32, p1 - base);                    // multiple of 4
        for (int j = 0; j < cnt; j += 4) {
            int s0 = __shfl_sync(0xffffffffu, s, j);
            int s1 = __shfl_sync(0xffffffffu, s, j + 1);
            int s2 = __shfl_sync(0xffffffffu, s, j + 2);
            int s3 = __shfl_sync(0xffffffffu, s, j + 3);
            float v0 = __shfl_sync(0xffffffffu, v, j);
            float v1 = __shfl_sync(0xffffffffu, v, j + 1);
            float v2 = __shfl_sync(0xffffffffu, v, j + 2);
            float v3 = __shfl_sync(0xffffffffu, v, j + 3);
            uint4 g0 = Xb[s0 * 256 + sub];
            uint4 g1 = Xb[s1 * 256 + sub];
            uint4 g2 = Xb[s2 * 256 + sub];
            uint4 g3 = Xb[s3 * 256 + sub];
            acc8(acc, g0, v0);
            acc8(acc, g1, v1);
            acc8(acc, g2, v2);
            acc8(acc, g3, v3);
        }
    }
}

// ZERO (pass1 only): 16 blocks re-zero counters/degrees for the NEXT call.
// Safe: k_pre/k_scan/k_fill (this call) already consumed them; no later kernel reads them.
template <bool CHEB, bool STREAMST, bool ZERO>
__global__ void __launch_bounds__(256) k_spmm(
    const int* __restrict__ ptr, const uint2* __restrict__ edges,
    const __half* __restrict__ X, const __half* __restrict__ XM,
    __half* __restrict__ T)
{
    if (ZERO && blockIdx.y == 0 && blockIdx.x < 16) {
#pragma unroll
        for (int k = 0; k < 4; ++k) {
            int ii = blockIdx.x * 1024 + k * 256 + threadIdx.x;
            g_cnt1[ii] = 0; g_cnt2[ii] = 0;
            g_degr[ii] = 0.f; g_degc[ii] = 0.f;
        }
    }

    int lane = threadIdx.x & 31;
    int n = blockIdx.x * 8 + (threadIdx.x >> 5);
    int quad = blockIdx.y;                               // batches [quad*4, quad*4+4)
    int sub = (quad * 4 + (lane >> 3)) * 8 + (lane & 7); // uint4 index within 4KB node block

    int p0 = ptr[n], p1 = ptr[n + 1];                    // segment length multiple of 4
    float2 acc[4] = {{0.f,0.f},{0.f,0.f},{0.f,0.f},{0.f,0.f}};
    spmm_body(edges, (const uint4*)X, p0, p1, lane, sub, acc);

    size_t o = (size_t)n * 256 + sub;                    // uint4 units
    if (CHEB) {
        uint4 mg = __ldcs((const uint4*)XM + o);         // streamed, evict-first
        __half2* mh = (__half2*)&mg;
#pragma unroll
        for (int k = 0; k < 4; ++k) {
            float2 f = __half22float2(mh[k]);
            acc[k].x = 2.f * acc[k].x - f.x;
            acc[k].y = 2.f * acc[k].y - f.y;
        }
    }
    uint4 r;
    __half2* rh = (__half2*)&r;
#pragma unroll
    for (int k = 0; k < 4; ++k) rh[k] = __floats2half2_rn(acc[k].x, acc[k].y);
    if (STREAMST) __stcs((uint4*)T + o, r);
    else          ((uint4*)T)[o] = r;
}

// fused pass2 (z=0: T2 = 2*S1@T1 - Xh, streaming store) and
//       pass3 (z=1: T3 = S2@T1, cached store) — both gather T1 only.
__global__ void __launch_bounds__(256) k_spmm23(
    const int* __restrict__ ptr1, const uint2* __restrict__ e1,
    const int* __restrict__ ptr2, const uint2* __restrict__ e2,
    const __half* __restrict__ T1, const __half* __restrict__ Xh,
    __half* __restrict__ T2, __half* __restrict__ T3)
{
    int lane = threadIdx.x & 31;
    int n = blockIdx.x * 8 + (threadIdx.x >> 5);
    int quad = blockIdx.y;
    int sub = (quad * 4 + (lane >> 3)) * 8 + (lane & 7);
    bool pass3 = (blockIdx.z != 0);

    const int* ptr = pass3 ? ptr2 : ptr1;
    const uint2* edges = pass3 ? e2 : e1;

    int p0 = ptr[n], p1 = ptr[n + 1];
    float2 acc[4] = {{0.f,0.f},{0.f,0.f},{0.f,0.f},{0.f,0.f}};
    spmm_body(edges, (const uint4*)T1, p0, p1, lane, sub, acc);

    size_t o = (size_t)n * 256 + sub;
    if (!pass3) {   // Chebyshev epilogue + streaming store to T2
        uint4 mg = __ldcs((const uint4*)Xh + o);
        __half2* mh = (__half2*)&mg;
#pragma unroll
        for (int k = 0; k < 4; ++k) {
            float2 f = __half22float2(mh[k]);
            acc[k].x = 2.f * acc[k].x - f.x;
            acc[k].y = 2.f * acc[k].y - f.y;
        }
        uint4 r;
        __half2* rh = (__half2*)&r;
#pragma unroll
        for (int k = 0; k < 4; ++k) rh[k] = __floats2half2_rn(acc[k].x, acc[k].y);
        __stcs((uint4*)T2 + o, r);
    } else {        // plain store to T3 (gathered by pass4 -> cached)
        uint4 r;
        __half2* rh = (__half2*)&r;
#pragma unroll
        for (int k = 0; k < 4; ++k) rh[k] = __floats2half2_rn(acc[k].x, acc[k].y);
        ((uint4*)T3)[o] = r;
    }
}

// ---------------- tensor-core projection (W convert fused into smem fill) ----------------
// 1024 blocks x 8 warps; each warp sweeps 4 consecutive 16-row tiles.
__global__ void __launch_bounds__(256) k_gemm_tc(
    const __half* __restrict__ Xh, const __half* __restrict__ T1,
    const __half* __restrict__ T2, const __half* __restrict__ T3,
    const __half* __restrict__ T4, const float* __restrict__ W,
    const float* __restrict__ bias, float* __restrict__ out)
{
    __shared__ __half Wsh[MM * DD * DD];        // 40 KB, loaded + converted ONCE per block
    __shared__ float  Bsh[16 * 64];
    int tid = threadIdx.x;
    int warp = tid >> 5;

    // Wsh[(m*64+k)*64+o] = half(W[(k*5+m)*64+o]) — float4-vectorized permute+convert
#pragma unroll
    for (int i = tid; i < MM * DD * DD / 4; i += 256) {
        int m  = i >> 10;           // i / 1024
        int k  = (i >> 4) & 63;
        int o4 = i & 15;
        float4 v = *(const float4*)(W + (size_t)(k * MM + m) * DD + o4 * 4);
        ((__half2*)Wsh)[(m * 64 + k) * 32 + o4 * 2]     = __floats2half2_rn(v.x, v.y);
        ((__half2*)Wsh)[(m * 64 + k) * 32 + o4 * 2 + 1] = __floats2half2_rn(v.z, v.w);
    }
#pragma unroll
    for (int i = tid; i < 16 * 64; i += 256) Bsh[i] = bias[i & 63];
    __syncthreads();

    const __half* bufs[5] = {Xh, T1, T2, T3, T4};

#pragma unroll
    for (int t = 0; t < 4; ++t) {
        int tile = (blockIdx.x * 8 + warp) * 4 + t;
        int r0 = tile * 16;                 // global A row
        int n  = r0 >> 5;
        int b0 = r0 & 31;                   // 0 or 16

        wmma::fragment<wmma::accumulator, 16, 16, 16, float> c[4];
#pragma unroll
        for (int j = 0; j < 4; ++j)
            wmma::load_matrix_sync(c[j], &Bsh[j * 16], 64, wmma::mem_row_major);

#pragma unroll
        for (int m = 0; m < 5; ++m) {
            const __half* A = bufs[m] + (size_t)r0 * DD;
#pragma unroll
            for (int kt = 0; kt < 4; ++kt) {
                wmma::fragment<wmma::matrix_a, 16, 16, 16, __half, wmma::row_major> a;
                wmma::load_matrix_sync(a, A + kt * 16, 64);
#pragma unroll
                for (int j = 0; j < 4; ++j) {
                    wmma::fragment<wmma::matrix_b, 16, 16, 16, __half, wmma::row_major> b;
                    wmma::load_matrix_sync(b, &Wsh[(m * 64 + kt * 16) * 64 + j * 16], 64);
                    wmma::mma_sync(c[j], a, b, c[j]);
                }
            }
        }
        float* ob = out + ((size_t)b0 * NN + n) * DD;
#pragma unroll
        for (int j = 0; j < 4; ++j)
            wmma::store_matrix_sync(ob + j * 16, c[j], NN * DD, wmma::mem_row_major);
    }
}

// ---------------- launch ----------------
extern "C" void kernel_launch(void* const* d_in, const int* in_sizes, int n_in,
                              void* d_out, int out_size)
{
    const float* inputs  = (const float*)d_in[0];   // [B, N, D]
    const float* adj     = (const float*)d_in[1];   // [E]
    const int*   rows    = (const int*)d_in[2];     // [E]
    const int*   cols    = (const int*)d_in[3];     // [E]
    const float* weights = (const float*)d_in[4];   // [D*M, OUT]
    const float* biases  = (const float*)d_in[5];   // [1, OUT]
    float* out = (float*)d_out;                     // [B, N, OUT]
    (void)in_sizes; (void)n_in; (void)out_size;

    void *pP1, *pP2, *pE1, *pE2, *pX, *pT1, *pT2, *pT3, *pT4;
    cudaGetSymbolAddress(&pP1, g_ptr1);
    cudaGetSymbolAddress(&pP2, g_ptr2);
    cudaGetSymbolAddress(&pE1, g_e1);
    cudaGetSymbolAddress(&pE2, g_e2);
    cudaGetSymbolAddress(&pX,  g_Xh);
    cudaGetSymbolAddress(&pT1, g_T1);
    cudaGetSymbolAddress(&pT2, g_T2);
    cudaGetSymbolAddress(&pT3, g_T3);
    cudaGetSymbolAddress(&pT4, g_T4);

    // counters/degrees arrive zeroed (module-load init on call 1; pass1's ZERO
    // blocks re-zero them at the end of every call)
    k_pre<<<EDGE_BLOCKS + CVT_BLOCKS, 256>>>(rows, cols, adj, inputs);
    k_scan<<<dim3(16, 2), 1024>>>();
    k_fill<<<(EE + 255) / 256, 256>>>(rows, cols, adj);

    dim3 sg(NN / 8, 8);
    // pass1: T1 = S1 @ X0  (+ counter re-zero for next call)
    k_spmm<false, false, true><<<sg, 256>>>((const int*)pP1, (const uint2*)pE1,
                                            (const __half*)pX, nullptr, (__half*)pT1);
    // pass2 ∥ pass3 fused: T2 = 2*S1@T1 - X0 ; T3 = S2@T1
    dim3 sg23(NN / 8, 8, 2);
    k_spmm23<<<sg23, 256>>>((const int*)pP1, (const uint2*)pE1,
                            (const int*)pP2, (const uint2*)pE2,
                            (const __half*)pT1, (const __half*)pX,
                            (__half*)pT2, (__half*)pT3);
    // pass4: T4 = 2*S2 @ T3 - T1  (T4 read by GEMM right after -> cached store, L2-resident)
    k_spmm<true, false, false><<<sg, 256>>>((const int*)pP2, (const uint2*)pE2,
                                            (const __half*)pT3, (const __half*)pT1, (__half*)pT4);

    k_gemm_tc<<<(BB * NN) / (4 * 8 * 16), 256>>>((const __half*)pX, (const __half*)pT1,
                                                 (const __half*)pT2, (const __half*)pT3,
                                                 (const __half*)pT4, weights, biases, out);
}

// round 15
// speedup vs baseline: 1.0310x; 1.0310x over previous
#include <cuda_runtime.h>
#include <cuda_fp16.h>
#include <mma.h>
#include <cstdint>

#define NN 16384
#define EE 524288
#define EPAD (EE + 4 * NN)
#define BB 32
#define DD 64
#define MM 5

using namespace nvcuda;

// ---------------- device scratch (static, allocation-free) ----------------
// fp16 operand buffers, TRANSPOSED layout: buf[(n*32 + b)*64 + d]
__device__ __half g_Xh[(size_t)BB * NN * DD];
__device__ __half g_T1[(size_t)BB * NN * DD];
__device__ __half g_T2[(size_t)BB * NN * DD];
__device__ __half g_T3[(size_t)BB * NN * DD];
__device__ __half g_T4[(size_t)BB * NN * DD];

// NOTE: zero-initialized at module load; re-zeroed by pass1 every call (see k_spmm<ZERO>)
__device__ float g_degr[NN];
__device__ float g_degc[NN];
__device__ int   g_cnt1[NN], g_cnt2[NN];
__device__ int   g_ptr1[NN + 1], g_ptr2[NN + 1];
__device__ int   g_cur1[NN], g_cur2[NN];
__device__ uint2 g_e1[EPAD], g_e2[EPAD];    // packed (src, val-bits)

#define CVT_BLOCKS 65536   // BB*NN*DD/2 half2 elems / 256 threads
#define EDGE_BLOCKS 2048   // EE / 256

// fused: blocks [0,EDGE_BLOCKS) = degree/histogram atomics;
//        blocks [EDGE_BLOCKS, EDGE_BLOCKS+CVT_BLOCKS) = X transpose-convert.
// inputs [b][n][d] fp32 -> g_Xh [(n*32+b)*64+d] fp16 (transpose b<->n)
__global__ void k_pre(const int* __restrict__ rows, const int* __restrict__ cols,
                      const float* __restrict__ adj, const float* __restrict__ X) {
    int bx = blockIdx.x;
    if (bx < EDGE_BLOCKS) {
        int e = bx * 256 + threadIdx.x;
        if (e >= EE) return;
        int r = rows[e], c = cols[e];
        float a = adj[e];
        atomicAdd(&g_degr[r], a);
        atomicAdd(&g_degc[c], a);
        atomicAdd(&g_cnt1[c], 1);   // S1 scatters to cols
        atomicAdd(&g_cnt2[r], 1);   // S2 scatters to rows
    } else {
        int i = (bx - EDGE_BLOCKS) * 256 + threadIdx.x;   // half2 index in TARGET
        if (i >= BB * NN * (DD / 2)) return;
        int dh = i & 31;
        int b  = (i >> 5) & 31;
        int n  = i >> 10;
        float2 v = ((const float2*)X)[((size_t)b * NN + n) * 32 + dh];
        ((__half2*)g_Xh)[i] = __floats2half2_rn(v.x, v.y);
    }
}

// ---------------- single-kernel scan (both CSRs via blockIdx.y) ----------------
__global__ void __launch_bounds__(1024) k_scan() {
    int y = blockIdx.y;
    int bx = blockIdx.x;
    const int* cnt = y ? g_cnt2 : g_cnt1;
    int i = bx * 1024 + threadIdx.x;
    int lane = threadIdx.x & 31, w = threadIdx.x >> 5;
    __shared__ int sh[32];

    // (1) intra-block exclusive scan of padded counts
    int c = (cnt[i] + 3) & ~3;
    int x = c;
#pragma unroll
    for (int o = 1; o < 32; o <<= 1) {
        int t = __shfl_up_sync(0xffffffffu, x, o);
        if (lane >= o) x += t;
    }
    if (lane == 31) sh[w] = x;
    __syncthreads();
    if (w == 0) {
        int t = sh[lane];
#pragma unroll
        for (int o = 1; o < 32; o <<= 1) {
            int u = __shfl_up_sync(0xffffffffu, t, o);
            if (lane >= o) t += u;
        }
        sh[lane] = t;
    }
    __syncthreads();
    int pre = x - c + (w ? sh[w - 1] : 0);   // exclusive prefix within block
    __syncthreads();                          // done with sh as scan buffer

    // (2) global block offset: sum padded counts in [0, bx*1024)
    int part = 0;
    for (int j = threadIdx.x; j < bx * 1024; j += 1024)
        part += (cnt[j] + 3) & ~3;
#pragma unroll
    for (int o = 16; o > 0; o >>= 1)
        part += __shfl_down_sync(0xffffffffu, part, o);
    if (lane == 0) sh[w] = part;
    __syncthreads();
    if (w == 0) {
        int t = sh[lane];
#pragma unroll
        for (int o = 16; o > 0; o >>= 1)
            t += __shfl_down_sync(0xffffffffu, t, o);
        if (lane == 0) sh[0] = t;
    }
    __syncthreads();
    int boff = sh[0];

    // (3) finalize
    int* ptr = y ? g_ptr2 : g_ptr1;
    int* cur = y ? g_cur2 : g_cur1;
    uint2* edges = y ? g_e2 : g_e1;
    int p = boff + pre;
    ptr[i] = p; cur[i] = p;
    int cn = cnt[i], cr = (cn + 3) & ~3;
    for (int q = p + cn; q < p + cr; ++q) edges[q] = make_uint2(0u, 0u);
    if (bx == 15 && threadIdx.x == 1023) ptr[NN] = p + cr;
    float* dg = y ? g_degc : g_degr;
    float d = dg[i];
    dg[i] = (d > 0.f) ? 1.f / d : 0.f;
}

// fused: one edge-list read fills both CSRs (packed 8B stores)
__global__ void k_fill(const int* __restrict__ rows, const int* __restrict__ cols,
                       const float* __restrict__ adj) {
    int e = blockIdx.x * blockDim.x + threadIdx.x;
    if (e >= EE) return;
    int r = rows[e], c = cols[e];
    float a = adj[e];
    int p = atomicAdd(&g_cur1[c], 1);
    g_e1[p] = make_uint2((unsigned)r, __float_as_uint(a * g_degr[r]));
    int q = atomicAdd(&g_cur2[r], 1);
    g_e2[q] = make_uint2((unsigned)c, __float_as_uint(a * g_degc[c]));
}

// ---------------- SpMM mainloop: warp = (dst node, 4 batches) ----------------
__device__ __forceinline__ void acc8(float2* acc, uint4 g, float v) {
    __half2* h = (__half2*)&g;
#pragma unroll
    for (int k = 0; k < 4; ++k) {
        float2 f = __half22float2(h[k]);
        acc[k].x = fmaf(v, f.x, acc[k].x);
        acc[k].y = fmaf(v, f.y, acc[k].y);
    }
}

// one 4-edge block: broadcast metadata, 4 independent LDG.128 gathers, 32 FMAs
__device__ __forceinline__ void edge4(
    const uint4* __restrict__ Xb, int s, float v, int j, int sub, float2* acc)
{
    int s0 = __shfl_sync(0xffffffffu, s, j);
    int s1 = __shfl_sync(0xffffffffu, s, j + 1);
    int s2 = __shfl_sync(0xffffffffu, s, j + 2);
    int s3 = __shfl_sync(0xffffffffu, s, j + 3);
    float v0 = __shfl_sync(0xffffffffu, v, j);
    float v1 = __shfl_sync(0xffffffffu, v, j + 1);
    float v2 = __shfl_sync(0xffffffffu, v, j + 2);
    float v3 = __shfl_sync(0xffffffffu, v, j + 3);
    uint4 g0 = Xb[s0 * 256 + sub];
    uint4 g1 = Xb[s1 * 256 + sub];
    uint4 g2 = Xb[s2 * 256 + sub];
    uint4 g3 = Xb[s3 * 256 + sub];
    acc8(acc, g0, v0);
    acc8(acc, g1, v1);
    acc8(acc, g2, v2);
    acc8(acc, g3, v3);
}

// accumulates 4-batch slice for dst n over [p0,p1).
// Full 32-edge chunks use a constant-bound (fully unrolled) inner loop;
// the final partial chunk (<32, multiple of 4) takes the dynamic path.
__device__ __forceinline__ void spmm_body(
    const uint2* __restrict__ edges, const uint4* __restrict__ Xb,
    int p0, int p1, int lane, int sub, float2* acc)
{
    int base = p0;
    for (; base + 32 <= p1; base += 32) {
        uint2 e = edges[base + lane];
        int s = (int)e.x; float v = __uint_as_float(e.y);
#pragma unroll
        for (int j = 0; j < 32; j += 4)
            edge4(Xb, s, v, j, sub, acc);
    }
    if (base < p1) {
        int idx = base + lane;
        int s = 0; float v = 0.f;
        if (idx < p1) {
            uint2 e = edges[idx];
            s = (int)e.x; v = __uint_as_float(e.y);
        }
        int cnt = p1 - base;                 // multiple of 4, < 32
        for (int j = 0; j < cnt; j += 4)
            edge4(Xb, s, v, j, sub, acc);
    }
}

// ZERO (pass1 only): 16 blocks re-zero counters/degrees for the NEXT call.
// Safe: k_pre/k_scan/k_fill (this call) already consumed them; no later kernel reads them.
template <bool CHEB, bool STREAMST, bool ZERO>
__global__ void __launch_bounds__(256, 6) k_spmm(
    const int* __restrict__ ptr, const uint2* __restrict__ edges,
    const __half* __restrict__ X, const __half* __restrict__ XM,
    __half* __restrict__ T)
{
    if (ZERO && blockIdx.y == 0 && blockIdx.x < 16) {
#pragma unroll
        for (int k = 0; k < 4; ++k) {
            int ii = blockIdx.x * 1024 + k * 256 + threadIdx.x;
            g_cnt1[ii] = 0; g_cnt2[ii] = 0;
            g_degr[ii] = 0.f; g_degc[ii] = 0.f;
        }
    }

    int lane = threadIdx.x & 31;
    int n = blockIdx.x * 8 + (threadIdx.x >> 5);
    int quad = blockIdx.y;                               // batches [quad*4, quad*4+4)
    int sub = (quad * 4 + (lane >> 3)) * 8 + (lane & 7); // uint4 index within 4KB node block

    int p0 = ptr[n], p1 = ptr[n + 1];                    // segment length multiple of 4
    float2 acc[4] = {{0.f,0.f},{0.f,0.f},{0.f,0.f},{0.f,0.f}};
    spmm_body(edges, (const uint4*)X, p0, p1, lane, sub, acc);

    size_t o = (size_t)n * 256 + sub;                    // uint4 units
    if (CHEB) {
        uint4 mg = __ldcs((const uint4*)XM + o);         // streamed, evict-first
        __half2* mh = (__half2*)&mg;
#pragma unroll
        for (int k = 0; k < 4; ++k) {
            float2 f = __half22float2(mh[k]);
            acc[k].x = 2.f * acc[k].x - f.x;
            acc[k].y = 2.f * acc[k].y - f.y;
        }
    }
    uint4 r;
    __half2* rh = (__half2*)&r;
#pragma unroll
    for (int k = 0; k < 4; ++k) rh[k] = __floats2half2_rn(acc[k].x, acc[k].y);
    if (STREAMST) __stcs((uint4*)T + o, r);
    else          ((uint4*)T)[o] = r;
}

// fused pass2 (z=0: T2 = 2*S1@T1 - Xh, streaming store) and
//       pass3 (z=1: T3 = S2@T1, cached store) — both gather T1 only.
__global__ void __launch_bounds__(256, 6) k_spmm23(
    const int* __restrict__ ptr1, const uint2* __restrict__ e1,
    const int* __restrict__ ptr2, const uint2* __restrict__ e2,
    const __half* __restrict__ T1, const __half* __restrict__ Xh,
    __half* __restrict__ T2, __half* __restrict__ T3)
{
    int lane = threadIdx.x & 31;
    int n = blockIdx.x * 8 + (threadIdx.x >> 5);
    int quad = blockIdx.y;
    int sub = (quad * 4 + (lane >> 3)) * 8 + (lane & 7);
    bool pass3 = (blockIdx.z != 0);

    const int* ptr = pass3 ? ptr2 : ptr1;
    const uint2* edges = pass3 ? e2 : e1;

    int p0 = ptr[n], p1 = ptr[n + 1];
    float2 acc[4] = {{0.f,0.f},{0.f,0.f},{0.f,0.f},{0.f,0.f}};
    spmm_body(edges, (const uint4*)T1, p0, p1, lane, sub, acc);

    size_t o = (size_t)n * 256 + sub;
    if (!pass3) {   // Chebyshev epilogue + streaming store to T2
        uint4 mg = __ldcs((const uint4*)Xh + o);
        __half2* mh = (__half2*)&mg;
#pragma unroll
        for (int k = 0; k < 4; ++k) {
            float2 f = __half22float2(mh[k]);
            acc[k].x = 2.f * acc[k].x - f.x;
            acc[k].y = 2.f * acc[k].y - f.y;
        }
        uint4 r;
        __half2* rh = (__half2*)&r;
#pragma unroll
        for (int k = 0; k < 4; ++k) rh[k] = __floats2half2_rn(acc[k].x, acc[k].y);
        __stcs((uint4*)T2 + o, r);
    } else {        // plain store to T3 (gathered by pass4 -> cached)
        uint4 r;
        __half2* rh = (__half2*)&r;
#pragma unroll
        for (int k = 0; k < 4; ++k) rh[k] = __floats2half2_rn(acc[k].x, acc[k].y);
        ((uint4*)T3)[o] = r;
    }
}

// ---------------- tensor-core projection (W convert fused into smem fill) ----------------
// 1024 blocks x 8 warps; each warp sweeps 4 consecutive 16-row tiles.
__global__ void __launch_bounds__(256) k_gemm_tc(
    const __half* __restrict__ Xh, const __half* __restrict__ T1,
    const __half* __restrict__ T2, const __half* __restrict__ T3,
    const __half* __restrict__ T4, const float* __restrict__ W,
    const float* __restrict__ bias, float* __restrict__ out)
{
    __shared__ __half Wsh[MM * DD * DD];        // 40 KB, loaded + converted ONCE per block
    __shared__ float  Bsh[16 * 64];
    int tid = threadIdx.x;
    int warp = tid >> 5;

    // Wsh[(m*64+k)*64+o] = half(W[(k*5+m)*64+o]) — float4-vectorized permute+convert
#pragma unroll
    for (int i = tid; i < MM * DD * DD / 4; i += 256) {
        int m  = i >> 10;           // i / 1024
        int k  = (i >> 4) & 63;
        int o4 = i & 15;
        float4 v = *(const float4*)(W + (size_t)(k * MM + m) * DD + o4 * 4);
        ((__half2*)Wsh)[(m * 64 + k) * 32 + o4 * 2]     = __floats2half2_rn(v.x, v.y);
        ((__half2*)Wsh)[(m * 64 + k) * 32 + o4 * 2 + 1] = __floats2half2_rn(v.z, v.w);
    }
#pragma unroll
    for (int i = tid; i < 16 * 64; i += 256) Bsh[i] = bias[i & 63];
    __syncthreads();

    const __half* bufs[5] = {Xh, T1, T2, T3, T4};

#pragma unroll
    for (int t = 0; t < 4; ++t) {
        int tile = (blockIdx.x * 8 + warp) * 4 + t;
        int r0 = tile * 16;                 // global A row
        int n  = r0 >> 5;
        int b0 = r0 & 31;                   // 0 or 16

        wmma::fragment<wmma::accumulator, 16, 16, 16, float> c[4];
#pragma unroll
        for (int j = 0; j < 4; ++j)
            wmma::load_matrix_sync(c[j], &Bsh[j * 16], 64, wmma::mem_row_major);

#pragma unroll
        for (int m = 0; m < 5; ++m) {
            const __half* A = bufs[m] + (size_t)r0 * DD;
#pragma unroll
            for (int kt = 0; kt < 4; ++kt) {
                wmma::fragment<wmma::matrix_a, 16, 16, 16, __half, wmma::row_major> a;
                wmma::load_matrix_sync(a, A + kt * 16, 64);
#pragma unroll
                for (int j = 0; j < 4; ++j) {
                    wmma::fragment<wmma::matrix_b, 16, 16, 16, __half, wmma::row_major> b;
                    wmma::load_matrix_sync(b, &Wsh[(m * 64 + kt * 16) * 64 + j * 16], 64);
                    wmma::mma_sync(c[j], a, b, c[j]);
                }
            }
        }
        float* ob = out + ((size_t)b0 * NN + n) * DD;
#pragma unroll
        for (int j = 0; j < 4; ++j)
            wmma::store_matrix_sync(ob + j * 16, c[j], NN * DD, wmma::mem_row_major);
    }
}

// ---------------- launch ----------------
extern "C" void kernel_launch(void* const* d_in, const int* in_sizes, int n_in,
                              void* d_out, int out_size)
{
    const float* inputs  = (const float*)d_in[0];   // [B, N, D]
    const float* adj     = (const float*)d_in[1];   // [E]
    const int*   rows    = (const int*)d_in[2];     // [E]
    const int*   cols    = (const int*)d_in[3];     // [E]
    const float* weights = (const float*)d_in[4];   // [D*M, OUT]
    const float* biases  = (const float*)d_in[5];   // [1, OUT]
    float* out = (float*)d_out;                     // [B, N, OUT]
    (void)in_sizes; (void)n_in; (void)out_size;

    void *pP1, *pP2, *pE1, *pE2, *pX, *pT1, *pT2, *pT3, *pT4;
    cudaGetSymbolAddress(&pP1, g_ptr1);
    cudaGetSymbolAddress(&pP2, g_ptr2);
    cudaGetSymbolAddress(&pE1, g_e1);
    cudaGetSymbolAddress(&pE2, g_e2);
    cudaGetSymbolAddress(&pX,  g_Xh);
    cudaGetSymbolAddress(&pT1, g_T1);
    cudaGetSymbolAddress(&pT2, g_T2);
    cudaGetSymbolAddress(&pT3, g_T3);
    cudaGetSymbolAddress(&pT4, g_T4);

    // counters/degrees arrive zeroed (module-load init on call 1; pass1's ZERO
    // blocks re-zero them at the end of every call)
    k_pre<<<EDGE_BLOCKS + CVT_BLOCKS, 256>>>(rows, cols, adj, inputs);
    k_scan<<<dim3(16, 2), 1024>>>();
    k_fill<<<(EE + 255) / 256, 256>>>(rows, cols, adj);

    dim3 sg(NN / 8, 8);
    // pass1: T1 = S1 @ X0  (+ counter re-zero for next call)
    k_spmm<false, false, true><<<sg, 256>>>((const int*)pP1, (const uint2*)pE1,
                                            (const __half*)pX, nullptr, (__half*)pT1);
    // pass2 ∥ pass3 fused: T2 = 2*S1@T1 - X0 ; T3 = S2@T1
    dim3 sg23(NN / 8, 8, 2);
    k_spmm23<<<sg23, 256>>>((const int*)pP1, (const uint2*)pE1,
                            (const int*)pP2, (const uint2*)pE2,
                            (const __half*)pT1, (const __half*)pX,
                            (__half*)pT2, (__half*)pT3);
    // pass4: T4 = 2*S2 @ T3 - T1  (T4 read by GEMM right after -> cached store)
    k_spmm<true, false, false><<<sg, 256>>>((const int*)pP2, (const uint2*)pE2,
                                            (const __half*)pT3, (const __half*)pT1, (__half*)pT4);

    k_gemm_tc<<<(BB * NN) / (4 * 8 * 16), 256>>>((const __half*)pX, (const __half*)pT1,
                                                 (const __half*)pT2, (const __half*)pT3,
                                                 (const __half*)pT4, weights, biases, out);
}